// round 2
// baseline (speedup 1.0000x reference)
#include <cuda_runtime.h>

// ---------------------------------------------------------------------------
// CorticalGrid: 32x32 grid of predictive-coding columns, 20 relaxation steps.
// One CTA per column; 20 sequential step launches; fp32 register-blocked GEMMs.
// R2: smem diet (72KB -> 3 CTAs/SM), register ctx/patch prefetch, fast tanh,
//     shuffle reduction, float4 sg stores.
// ---------------------------------------------------------------------------

constexpr int GRID_H = 32, GRID_W = 32;
constexpr int NCOL   = GRID_H * GRID_W;   // 1024
constexpr int BATCH  = 64;
constexpr int OBJ    = 64;
constexpr int LOC    = 16;
constexpr int SEN    = 64;
constexpr int STEPS  = 20;
constexpr float ETA  = 0.05f;

constexpr int COL_OBJ = BATCH * OBJ;   // 4096
constexpr int COL_LOC = BATCH * LOC;   // 1024
constexpr int COL_SEN = BATCH * SEN;   // 4096

// Device-global scratch (allocation-free rule: __device__ arrays only)
__device__ float g_xobj0[NCOL * COL_OBJ];
__device__ float g_xobj1[NCOL * COL_OBJ];
__device__ float g_xloc [NCOL * COL_LOC];
__device__ float g_patch[NCOL * COL_SEN];
__device__ float g_WtObj[NCOL * OBJ * SEN];    // [n][s*64+o]
__device__ float g_epart[STEPS * NCOL];

// ---------------------------------------------------------------------------
// Prep: zero state, slice patches into (n, b, s), build transposed W_obj.
// ---------------------------------------------------------------------------
__global__ void prep_kernel(const float* __restrict__ gin,
                            const float* __restrict__ Wobj)
{
    const int stride = gridDim.x * blockDim.x;
    for (int i = blockIdx.x * blockDim.x + threadIdx.x; i < NCOL * COL_SEN; i += stride) {
        g_xobj0[i] = 0.0f;
        const int n = i >> 12, r = i & 4095;
        const int b  = r >> 6, s = r & 63;
        const int gh = n >> 5, gw = n & 31;
        const int ph = s >> 3, pw = s & 7;
        g_patch[i] = gin[b * 65536 + (gh * 8 + ph) * 256 + gw * 8 + pw];
        const int o = r >> 6, ss = r & 63;
        g_WtObj[(n << 12) + ss * 64 + o] = Wobj[i];
    }
    for (int i = blockIdx.x * blockDim.x + threadIdx.x; i < NCOL * COL_LOC; i += stride)
        g_xloc[i] = 0.0f;
}

__device__ __forceinline__ float fast_tanh(float u) {
    // 1 - 2/(e^{2u}+1): MUFU.EX2 + MUFU.RCP path, rel err ~1e-6.
    float e = __expf(2.0f * u);
    return 1.0f - __fdividef(2.0f, e + 1.0f);
}

// ---------------------------------------------------------------------------
// One relaxation step. CTA n owns column n. 256 threads, 3 CTAs/SM.
// Shared: sW 4096 | sWt 4096 | sWl 1024 | sx 4096 | sxl 1024 | sg 4096
//         = 18432 floats = 73728 B.
// ---------------------------------------------------------------------------
__global__ void __launch_bounds__(256, 3) step_kernel(
    const float* __restrict__ Wobj,
    const float* __restrict__ Wloc,
    float* __restrict__ out_x,
    int step)
{
    extern __shared__ float sh[];
    float* sW   = sh;            // [o*64+s]
    float* sWt  = sh + 4096;     // [s*64+o]
    float* sWl  = sh + 8192;     // [l*64+s]
    float* sx   = sh + 9216;     // [b*64+o]
    float* sxl  = sh + 13312;    // [b*16+l]
    float* sg   = sh + 14336;    // [b*64+s]

    const int n   = blockIdx.x;
    const int tid = threadIdx.x;

    const float* __restrict__ xin = (step & 1) ? g_xobj1 : g_xobj0;
    float* __restrict__ xoutbuf   = (step & 1) ? g_xobj0 : g_xobj1;
    float* __restrict__ xout      = (step == STEPS - 1) ? out_x : xoutbuf;

    // ---- load column-local tensors into shared ----
    {
        const float4* s1 = (const float4*)(Wobj    + ((long)n << 12));
        const float4* s2 = (const float4*)(g_WtObj + ((long)n << 12));
        const float4* s3 = (const float4*)(xin     + ((long)n << 12));
        float4* d1 = (float4*)sW; float4* d2 = (float4*)sWt; float4* d3 = (float4*)sx;
        #pragma unroll
        for (int k = 0; k < 4; k++) {
            d1[tid + 256 * k] = s1[tid + 256 * k];
            d2[tid + 256 * k] = s2[tid + 256 * k];
            d3[tid + 256 * k] = s3[tid + 256 * k];
        }
        ((float4*)sWl )[tid] = ((const float4*)(Wloc   + ((long)n << 10)))[tid];
        ((float4*)sxl )[tid] = ((const float4*)(g_xloc + ((long)n << 10)))[tid];
    }
    __syncthreads();

    const int b0 = (tid >> 4) << 2;   // batch tile base
    const int c0 = (tid & 15) << 2;   // s-tile (forward) / o-tile (backward)

    // ---- forward: u = x_obj @ W_obj + x_loc @ W_loc ----
    float acc[4][4];
    #pragma unroll
    for (int i = 0; i < 4; i++) { acc[i][0] = 0.f; acc[i][1] = 0.f; acc[i][2] = 0.f; acc[i][3] = 0.f; }

    #pragma unroll 4
    for (int o = 0; o < OBJ; o += 4) {
        float xv[4][4], wv[4][4];
        #pragma unroll
        for (int i = 0; i < 4; i++) { float4 t = *(const float4*)&sx[(b0 + i) * 64 + o];  xv[i][0]=t.x; xv[i][1]=t.y; xv[i][2]=t.z; xv[i][3]=t.w; }
        #pragma unroll
        for (int j = 0; j < 4; j++) { float4 t = *(const float4*)&sW[(o + j) * 64 + c0]; wv[j][0]=t.x; wv[j][1]=t.y; wv[j][2]=t.z; wv[j][3]=t.w; }
        #pragma unroll
        for (int i = 0; i < 4; i++)
            #pragma unroll
            for (int c = 0; c < 4; c++)
                acc[i][c] += xv[i][0]*wv[0][c] + xv[i][1]*wv[1][c] + xv[i][2]*wv[2][c] + xv[i][3]*wv[3][c];
    }

    // prefetch patch tiles (L2) while the loc-forward loop runs
    float4 p4[4];
    #pragma unroll
    for (int i = 0; i < 4; i++)
        p4[i] = *(const float4*)&g_patch[((long)n << 12) + (b0 + i) * 64 + c0];

    #pragma unroll
    for (int l = 0; l < LOC; l += 4) {
        float xv[4][4], wv[4][4];
        #pragma unroll
        for (int i = 0; i < 4; i++) { float4 t = *(const float4*)&sxl[(b0 + i) * 16 + l]; xv[i][0]=t.x; xv[i][1]=t.y; xv[i][2]=t.z; xv[i][3]=t.w; }
        #pragma unroll
        for (int j = 0; j < 4; j++) { float4 t = *(const float4*)&sWl[(l + j) * 64 + c0]; wv[j][0]=t.x; wv[j][1]=t.y; wv[j][2]=t.z; wv[j][3]=t.w; }
        #pragma unroll
        for (int i = 0; i < 4; i++)
            #pragma unroll
            for (int c = 0; c < 4; c++)
                acc[i][c] += xv[i][0]*wv[0][c] + xv[i][1]*wv[1][c] + xv[i][2]*wv[2][c] + xv[i][3]*wv[3][c];
    }

    // ---- pointwise: pred, eps, g, energy ----
    float e_acc = 0.f;
    #pragma unroll
    for (int i = 0; i < 4; i++) {
        float pv[4] = {p4[i].x, p4[i].y, p4[i].z, p4[i].w};
        float4 g4;
        float gg[4];
        #pragma unroll
        for (int c = 0; c < 4; c++) {
            float pr  = fast_tanh(acc[i][c]);
            float eps = pv[c] - pr;
            e_acc += eps * eps;
            gg[c] = eps * (1.0f - pr * pr);
        }
        g4.x = gg[0]; g4.y = gg[1]; g4.z = gg[2]; g4.w = gg[3];
        *(float4*)&sg[(b0 + i) * 64 + c0] = g4;
    }
    __syncthreads();

    // ---- lateral context into registers (L2 loads overlap backward GEMM) ----
    const int gh = n >> 5, gw = n & 31;
    const bool mu = gh > 0, md = gh < GRID_H - 1, ml = gw > 0, mr = gw < GRID_W - 1;
    const float inv = 1.0f / (float)((int)mu + (int)md + (int)ml + (int)mr);
    float4 cx[4];
    #pragma unroll
    for (int i = 0; i < 4; i++) {
        const int off = (b0 + i) * 64 + c0;
        float ax = 0.f, ay = 0.f, az = 0.f, aw = 0.f;
        if (mu) { float4 v = *(const float4*)&xin[(((long)(n - GRID_W)) << 12) + off]; ax += v.x; ay += v.y; az += v.z; aw += v.w; }
        if (md) { float4 v = *(const float4*)&xin[(((long)(n + GRID_W)) << 12) + off]; ax += v.x; ay += v.y; az += v.z; aw += v.w; }
        if (ml) { float4 v = *(const float4*)&xin[(((long)(n - 1))      << 12) + off]; ax += v.x; ay += v.y; az += v.z; aw += v.w; }
        if (mr) { float4 v = *(const float4*)&xin[(((long)(n + 1))      << 12) + off]; ax += v.x; ay += v.y; az += v.z; aw += v.w; }
        cx[i].x = ax * inv; cx[i].y = ay * inv; cx[i].z = az * inv; cx[i].w = aw * inv;
    }

    // ---- backward obj: dx_obj = g @ W_obj^T, update x_obj ----
    float acc2[4][4];
    #pragma unroll
    for (int i = 0; i < 4; i++) { acc2[i][0] = 0.f; acc2[i][1] = 0.f; acc2[i][2] = 0.f; acc2[i][3] = 0.f; }

    #pragma unroll 4
    for (int s = 0; s < SEN; s += 4) {
        float gv[4][4], wv[4][4];
        #pragma unroll
        for (int i = 0; i < 4; i++) { float4 t = *(const float4*)&sg[(b0 + i) * 64 + s];  gv[i][0]=t.x; gv[i][1]=t.y; gv[i][2]=t.z; gv[i][3]=t.w; }
        #pragma unroll
        for (int j = 0; j < 4; j++) { float4 t = *(const float4*)&sWt[(s + j) * 64 + c0]; wv[j][0]=t.x; wv[j][1]=t.y; wv[j][2]=t.z; wv[j][3]=t.w; }
        #pragma unroll
        for (int i = 0; i < 4; i++)
            #pragma unroll
            for (int c = 0; c < 4; c++)
                acc2[i][c] += gv[i][0]*wv[0][c] + gv[i][1]*wv[1][c] + gv[i][2]*wv[2][c] + gv[i][3]*wv[3][c];
    }
    #pragma unroll
    for (int i = 0; i < 4; i++) {
        float4 xo = *(const float4*)&sx[(b0 + i) * 64 + c0];
        float4 ov;
        ov.x = xo.x + ETA * (acc2[i][0] + cx[i].x - xo.x);
        ov.y = xo.y + ETA * (acc2[i][1] + cx[i].y - xo.y);
        ov.z = xo.z + ETA * (acc2[i][2] + cx[i].z - xo.z);
        ov.w = xo.w + ETA * (acc2[i][3] + cx[i].w - xo.w);
        *(float4*)&xout[((long)n << 12) + (b0 + i) * 64 + c0] = ov;
    }

    // ---- backward loc: dx_loc = g @ W_loc^T (rows of sWl, broadcast reads) ----
    {
        const int bl = tid >> 2;
        const int l0 = (tid & 3) << 2;
        float a3[4] = {0.f, 0.f, 0.f, 0.f};
        #pragma unroll 4
        for (int s = 0; s < SEN; s += 4) {
            float4 gq = *(const float4*)&sg[bl * 64 + s];
            #pragma unroll
            for (int lp = 0; lp < 4; lp++) {
                float4 w = *(const float4*)&sWl[(l0 + lp) * 64 + s];
                a3[lp] += gq.x * w.x + gq.y * w.y + gq.z * w.z + gq.w * w.w;
            }
        }
        float4 xl = *(const float4*)&sxl[bl * 16 + l0];
        float4 ov;
        ov.x = xl.x + ETA * a3[0]; ov.y = xl.y + ETA * a3[1];
        ov.z = xl.z + ETA * a3[2]; ov.w = xl.w + ETA * a3[3];
        *(float4*)&g_xloc[((long)n << 10) + bl * 16 + l0] = ov;
    }

    // ---- energy: warp shuffle reduce, then 8 partials via sg (reused) ----
    __syncthreads();   // all sg reads done
    #pragma unroll
    for (int w = 16; w > 0; w >>= 1)
        e_acc += __shfl_down_sync(0xffffffffu, e_acc, w);
    if ((tid & 31) == 0) sg[tid >> 5] = e_acc;
    __syncthreads();
    if (tid == 0) {
        float s = 0.f;
        #pragma unroll
        for (int w = 0; w < 8; w++) s += sg[w];
        g_epart[step * NCOL + n] = s;
    }
}

// ---------------------------------------------------------------------------
// Finalize: fixed-order sum of 1024 partials per step -> energy_hist.
// ---------------------------------------------------------------------------
__global__ void finalize_kernel(float* __restrict__ out)
{
    const int step = blockIdx.x;
    const int tid  = threadIdx.x;
    __shared__ float r[256];
    float s = g_epart[step * NCOL + tid]
            + g_epart[step * NCOL + tid + 256]
            + g_epart[step * NCOL + tid + 512]
            + g_epart[step * NCOL + tid + 768];
    r[tid] = s;
    __syncthreads();
    #pragma unroll
    for (int w = 128; w > 0; w >>= 1) {
        if (tid < w) r[tid] += r[tid + w];
        __syncthreads();
    }
    if (tid == 0) out[(long)NCOL * COL_OBJ + step] = 0.5f * r[0];
}

// ---------------------------------------------------------------------------
extern "C" void kernel_launch(void* const* d_in, const int* in_sizes, int n_in,
                              void* d_out, int out_size)
{
    const float* gin  = (const float*)d_in[0];  // global_input (64, 65536)
    const float* Wobj = (const float*)d_in[1];  // (1024, 64, 64)
    const float* Wloc = (const float*)d_in[2];  // (1024, 16, 64)
    float* out = (float*)d_out;                 // x_obj (1024*64*64) ++ energy (20)

    constexpr int SMEM_BYTES = 18432 * (int)sizeof(float);  // 73728
    cudaFuncSetAttribute(step_kernel, cudaFuncAttributeMaxDynamicSharedMemorySize, SMEM_BYTES);

    prep_kernel<<<1024, 256>>>(gin, Wobj);
    for (int step = 0; step < STEPS; step++) {
        step_kernel<<<NCOL, 256, SMEM_BYTES>>>(Wobj, Wloc, out, step);
    }
    finalize_kernel<<<STEPS, 256>>>(out);
}

// round 7
// speedup vs baseline: 1.0179x; 1.0179x over previous
#include <cuda_runtime.h>

// ---------------------------------------------------------------------------
// CorticalGrid: 32x32 grid of predictive-coding columns, 20 relaxation steps.
// R3 (4th resubmit — broker timeouts): single padded weight copy (stride 68,
// conflict-free in both GEMM directions), no g_WtObj mirror (working set
// ~76MB fits L2), work-stealing queue (grid=444) to kill wave quantization.
// ---------------------------------------------------------------------------

constexpr int GRID_H = 32, GRID_W = 32;
constexpr int NCOL   = GRID_H * GRID_W;   // 1024
constexpr int BATCH  = 64;
constexpr int OBJ    = 64;
constexpr int LOC    = 16;
constexpr int SEN    = 64;
constexpr int STEPS  = 20;
constexpr float ETA  = 0.05f;
constexpr int SWS    = 68;                // padded row stride for sW

constexpr int COL_OBJ = BATCH * OBJ;   // 4096
constexpr int COL_LOC = BATCH * LOC;   // 1024
constexpr int COL_SEN = BATCH * SEN;   // 4096

// Device-global scratch (allocation-free rule: __device__ arrays only)
__device__ float g_xobj0[NCOL * COL_OBJ];
__device__ float g_xobj1[NCOL * COL_OBJ];
__device__ float g_xloc [NCOL * COL_LOC];
__device__ float g_patch[NCOL * COL_SEN];
__device__ float g_epart[STEPS * NCOL];
__device__ int   g_q[32];                 // per-step work-stealing counters

// ---------------------------------------------------------------------------
// Prep: zero state & queues, slice patches into (n, b, s).
// ---------------------------------------------------------------------------
__global__ void prep_kernel(const float* __restrict__ gin)
{
    const int stride = gridDim.x * blockDim.x;
    const int t0 = blockIdx.x * blockDim.x + threadIdx.x;
    for (int i = t0; i < NCOL * COL_SEN; i += stride) {
        g_xobj0[i] = 0.0f;
        const int n = i >> 12, r = i & 4095;
        const int b  = r >> 6, s = r & 63;
        const int gh = n >> 5, gw = n & 31;
        const int ph = s >> 3, pw = s & 7;
        g_patch[i] = gin[b * 65536 + (gh * 8 + ph) * 256 + gw * 8 + pw];
    }
    for (int i = t0; i < NCOL * COL_LOC; i += stride)
        g_xloc[i] = 0.0f;
    if (t0 < 32) g_q[t0] = 0;
}

__device__ __forceinline__ float fast_tanh(float u) {
    float e = __expf(2.0f * u);
    return 1.0f - __fdividef(2.0f, e + 1.0f);
}

// ---------------------------------------------------------------------------
// One relaxation step. Grid = 444 CTAs, work-stealing over 1024 columns.
// Shared (floats): sW 4352 | sWl 1024 | sx 4096 | sxl 1024 | sg 4096 |
//                  sctx 4096 | bc 4   -> 18692 floats = 74768 B (3 CTAs/SM).
// ---------------------------------------------------------------------------
constexpr int SH_FLOATS = 4352 + 1024 + 4096 + 1024 + 4096 + 4096 + 4;

__global__ void __launch_bounds__(256, 3) step_kernel(
    const float* __restrict__ Wobj,
    const float* __restrict__ Wloc,
    float* __restrict__ out_x,
    int step)
{
    extern __shared__ float sh[];
    float* sW   = sh;            // [o*68 + s]   (padded)
    float* sWl  = sh + 4352;     // [l*64 + s]
    float* sx   = sh + 5376;     // [b*64 + o]
    float* sxl  = sh + 9472;     // [b*16 + l]
    float* sg   = sh + 10496;    // [b*64 + s]
    float* sctx = sh + 14592;    // [b*64 + o]
    int*   sbc  = (int*)(sh + 18688);

    const int tid = threadIdx.x;
    const int b0  = (tid >> 4) << 2;   // batch tile base (4 rows)
    const int c0  = (tid & 15) << 2;   // fwd s-tile base (4 cols, contiguous)
    const int oc  = tid & 15;          // bwd o base (stride-16 columns)

    const float* __restrict__ xin = (step & 1) ? g_xobj1 : g_xobj0;
    float* __restrict__ xoutbuf   = (step & 1) ? g_xobj0 : g_xobj1;
    float* __restrict__ xout      = (step == STEPS - 1) ? out_x : xoutbuf;

    for (;;) {
        if (tid == 0) sbc[0] = atomicAdd(&g_q[step], 1);
        __syncthreads();
        const int n = sbc[0];
        if (n >= NCOL) break;

        // ---- lateral context (L2 loads, issued early) -> sctx ----
        {
            const int gh = n >> 5, gw = n & 31;
            const bool mu = gh > 0, md = gh < GRID_H - 1, ml = gw > 0, mr = gw < GRID_W - 1;
            const float inv = 1.0f / (float)((int)mu + (int)md + (int)ml + (int)mr);
            #pragma unroll
            for (int i = 0; i < 4; i++) {
                const int off = (b0 + i) * 64 + c0;
                float ax = 0.f, ay = 0.f, az = 0.f, aw = 0.f;
                if (mu) { float4 v = *(const float4*)&xin[(((long)(n - GRID_W)) << 12) + off]; ax += v.x; ay += v.y; az += v.z; aw += v.w; }
                if (md) { float4 v = *(const float4*)&xin[(((long)(n + GRID_W)) << 12) + off]; ax += v.x; ay += v.y; az += v.z; aw += v.w; }
                if (ml) { float4 v = *(const float4*)&xin[(((long)(n - 1))      << 12) + off]; ax += v.x; ay += v.y; az += v.z; aw += v.w; }
                if (mr) { float4 v = *(const float4*)&xin[(((long)(n + 1))      << 12) + off]; ax += v.x; ay += v.y; az += v.z; aw += v.w; }
                float4 o4; o4.x = ax * inv; o4.y = ay * inv; o4.z = az * inv; o4.w = aw * inv;
                *(float4*)&sctx[off] = o4;
            }
        }

        // ---- fill smem: W (padded rows), x, Wl, xl ----
        {
            const float4* wsrc = (const float4*)(Wobj + ((long)n << 12));
            #pragma unroll
            for (int k = 0; k < 4; k++) {
                const int e = tid + 256 * k;        // float4 index
                const int o = e >> 4, s4 = e & 15;
                *(float4*)&sW[o * SWS + (s4 << 2)] = wsrc[e];
            }
            const float4* xsrc = (const float4*)(xin + ((long)n << 12));
            float4* xdst = (float4*)sx;
            #pragma unroll
            for (int k = 0; k < 4; k++)
                xdst[tid + 256 * k] = xsrc[tid + 256 * k];
            ((float4*)sWl)[tid] = ((const float4*)(Wloc   + ((long)n << 10)))[tid];
            ((float4*)sxl)[tid] = ((const float4*)(g_xloc + ((long)n << 10)))[tid];
        }
        __syncthreads();

        // ---- forward: u = x_obj @ W_obj + x_loc @ W_loc ----
        float acc[4][4];
        #pragma unroll
        for (int i = 0; i < 4; i++) { acc[i][0]=0.f; acc[i][1]=0.f; acc[i][2]=0.f; acc[i][3]=0.f; }

        #pragma unroll 4
        for (int o = 0; o < OBJ; o += 4) {
            float xv[4][4], wv[4][4];
            #pragma unroll
            for (int i = 0; i < 4; i++) { float4 t = *(const float4*)&sx[(b0 + i) * 64 + o];  xv[i][0]=t.x; xv[i][1]=t.y; xv[i][2]=t.z; xv[i][3]=t.w; }
            #pragma unroll
            for (int j = 0; j < 4; j++) { float4 t = *(const float4*)&sW[(o + j) * SWS + c0]; wv[j][0]=t.x; wv[j][1]=t.y; wv[j][2]=t.z; wv[j][3]=t.w; }
            #pragma unroll
            for (int i = 0; i < 4; i++)
                #pragma unroll
                for (int c = 0; c < 4; c++)
                    acc[i][c] += xv[i][0]*wv[0][c] + xv[i][1]*wv[1][c] + xv[i][2]*wv[2][c] + xv[i][3]*wv[3][c];
        }

        // prefetch patch tiles (L2) while the loc-forward loop runs
        float4 p4[4];
        #pragma unroll
        for (int i = 0; i < 4; i++)
            p4[i] = *(const float4*)&g_patch[((long)n << 12) + (b0 + i) * 64 + c0];

        #pragma unroll
        for (int l = 0; l < LOC; l += 4) {
            float xv[4][4], wv[4][4];
            #pragma unroll
            for (int i = 0; i < 4; i++) { float4 t = *(const float4*)&sxl[(b0 + i) * 16 + l]; xv[i][0]=t.x; xv[i][1]=t.y; xv[i][2]=t.z; xv[i][3]=t.w; }
            #pragma unroll
            for (int j = 0; j < 4; j++) { float4 t = *(const float4*)&sWl[(l + j) * 64 + c0]; wv[j][0]=t.x; wv[j][1]=t.y; wv[j][2]=t.z; wv[j][3]=t.w; }
            #pragma unroll
            for (int i = 0; i < 4; i++)
                #pragma unroll
                for (int c = 0; c < 4; c++)
                    acc[i][c] += xv[i][0]*wv[0][c] + xv[i][1]*wv[1][c] + xv[i][2]*wv[2][c] + xv[i][3]*wv[3][c];
        }

        // ---- pointwise: pred, eps, g, energy ----
        float e_acc = 0.f;
        #pragma unroll
        for (int i = 0; i < 4; i++) {
            float pv[4] = {p4[i].x, p4[i].y, p4[i].z, p4[i].w};
            float gg[4];
            #pragma unroll
            for (int c = 0; c < 4; c++) {
                float pr  = fast_tanh(acc[i][c]);
                float eps = pv[c] - pr;
                e_acc += eps * eps;
                gg[c] = eps * (1.0f - pr * pr);
            }
            float4 g4; g4.x = gg[0]; g4.y = gg[1]; g4.z = gg[2]; g4.w = gg[3];
            *(float4*)&sg[(b0 + i) * 64 + c0] = g4;
        }
        __syncthreads();

        // ---- backward obj: dx_obj = g @ W^T from the SAME sW copy ----
        // thread covers o = oc + 16j (lanes vary o by 1 -> conflict-free rows)
        float acc2[4][4];
        #pragma unroll
        for (int i = 0; i < 4; i++) { acc2[i][0]=0.f; acc2[i][1]=0.f; acc2[i][2]=0.f; acc2[i][3]=0.f; }

        #pragma unroll 4
        for (int s = 0; s < SEN; s += 4) {
            float gv[4][4], wv[4][4];
            #pragma unroll
            for (int i = 0; i < 4; i++) { float4 t = *(const float4*)&sg[(b0 + i) * 64 + s]; gv[i][0]=t.x; gv[i][1]=t.y; gv[i][2]=t.z; gv[i][3]=t.w; }
            #pragma unroll
            for (int j = 0; j < 4; j++) { float4 t = *(const float4*)&sW[(oc + 16 * j) * SWS + s]; wv[j][0]=t.x; wv[j][1]=t.y; wv[j][2]=t.z; wv[j][3]=t.w; }
            #pragma unroll
            for (int i = 0; i < 4; i++)
                #pragma unroll
                for (int j = 0; j < 4; j++)
                    acc2[i][j] += gv[i][0]*wv[j][0] + gv[i][1]*wv[j][1] + gv[i][2]*wv[j][2] + gv[i][3]*wv[j][3];
        }
        // update x_obj at o = oc + 16j (coalesced scalar stores)
        #pragma unroll
        for (int i = 0; i < 4; i++) {
            #pragma unroll
            for (int j = 0; j < 4; j++) {
                const int idx = (b0 + i) * 64 + oc + 16 * j;
                const float xo = sx[idx];
                const float cv = sctx[idx];
                xout[((long)n << 12) + idx] = xo + ETA * (acc2[i][j] + cv - xo);
            }
        }

        // ---- backward loc: dx_loc = g @ W_loc^T ----
        {
            const int bl = tid >> 2;
            const int l0 = (tid & 3) << 2;
            float a3[4] = {0.f, 0.f, 0.f, 0.f};
            #pragma unroll 4
            for (int s = 0; s < SEN; s += 4) {
                float4 gq = *(const float4*)&sg[bl * 64 + s];
                #pragma unroll
                for (int lp = 0; lp < 4; lp++) {
                    float4 w = *(const float4*)&sWl[(l0 + lp) * 64 + s];
                    a3[lp] += gq.x * w.x + gq.y * w.y + gq.z * w.z + gq.w * w.w;
                }
            }
            float4 xl = *(const float4*)&sxl[bl * 16 + l0];
            float4 ov;
            ov.x = xl.x + ETA * a3[0]; ov.y = xl.y + ETA * a3[1];
            ov.z = xl.z + ETA * a3[2]; ov.w = xl.w + ETA * a3[3];
            *(float4*)&g_xloc[((long)n << 10) + bl * 16 + l0] = ov;
        }

        // ---- energy: shuffle reduce + 8 partials via sg (reused) ----
        __syncthreads();
        #pragma unroll
        for (int w = 16; w > 0; w >>= 1)
            e_acc += __shfl_down_sync(0xffffffffu, e_acc, w);
        if ((tid & 31) == 0) sg[tid >> 5] = e_acc;
        __syncthreads();
        if (tid == 0) {
            float s = 0.f;
            #pragma unroll
            for (int w = 0; w < 8; w++) s += sg[w];
            g_epart[step * NCOL + n] = s;
        }
        // loop-top __syncthreads orders sg/sW reuse for the next column
    }
}

// ---------------------------------------------------------------------------
// Finalize: fixed-order sum of 1024 partials per step -> energy_hist.
// ---------------------------------------------------------------------------
__global__ void finalize_kernel(float* __restrict__ out)
{
    const int step = blockIdx.x;
    const int tid  = threadIdx.x;
    __shared__ float r[256];
    float s = g_epart[step * NCOL + tid]
            + g_epart[step * NCOL + tid + 256]
            + g_epart[step * NCOL + tid + 512]
            + g_epart[step * NCOL + tid + 768];
    r[tid] = s;
    __syncthreads();
    #pragma unroll
    for (int w = 128; w > 0; w >>= 1) {
        if (tid < w) r[tid] += r[tid + w];
        __syncthreads();
    }
    if (tid == 0) out[(long)NCOL * COL_OBJ + step] = 0.5f * r[0];
}

// ---------------------------------------------------------------------------
extern "C" void kernel_launch(void* const* d_in, const int* in_sizes, int n_in,
                              void* d_out, int out_size)
{
    const float* gin  = (const float*)d_in[0];  // global_input (64, 65536)
    const float* Wobj = (const float*)d_in[1];  // (1024, 64, 64)
    const float* Wloc = (const float*)d_in[2];  // (1024, 16, 64)
    float* out = (float*)d_out;                 // x_obj (1024*64*64) ++ energy (20)

    constexpr int SMEM_BYTES = SH_FLOATS * (int)sizeof(float);  // 74768
    cudaFuncSetAttribute(step_kernel, cudaFuncAttributeMaxDynamicSharedMemorySize, SMEM_BYTES);

    prep_kernel<<<1024, 256>>>(gin);
    for (int step = 0; step < STEPS; step++) {
        step_kernel<<<444, 256, SMEM_BYTES>>>(Wobj, Wloc, out, step);
    }
    finalize_kernel<<<STEPS, 256>>>(out);
}

// round 12
// speedup vs baseline: 1.0574x; 1.0387x over previous
#include <cuda_runtime.h>

// ---------------------------------------------------------------------------
// CorticalGrid: 32x32 grid of predictive-coding columns, 20 relaxation steps.
// R4 (4th resubmit — broker timeouts): packed f32x2 FMAs (FFMA2) in all GEMM
// loops — halves FMA-pipe time and issue pressure; static grid 1024; keeps
// R3's single stride-68 weight copy (conflict-free both directions).
// ---------------------------------------------------------------------------

constexpr int GRID_H = 32, GRID_W = 32;
constexpr int NCOL   = GRID_H * GRID_W;   // 1024
constexpr int BATCH  = 64;
constexpr int OBJ    = 64;
constexpr int LOC    = 16;
constexpr int SEN    = 64;
constexpr int STEPS  = 20;
constexpr float ETA  = 0.05f;
constexpr int SWS    = 68;                // padded row stride for sW

constexpr int COL_OBJ = BATCH * OBJ;   // 4096
constexpr int COL_LOC = BATCH * LOC;   // 1024
constexpr int COL_SEN = BATCH * SEN;   // 4096

// Device-global scratch (allocation-free rule: __device__ arrays only)
__device__ float g_xobj0[NCOL * COL_OBJ];
__device__ float g_xobj1[NCOL * COL_OBJ];
__device__ float g_xloc [NCOL * COL_LOC];
__device__ float g_patch[NCOL * COL_SEN];
__device__ float g_epart[STEPS * NCOL];

typedef unsigned long long u64;

__device__ __forceinline__ u64 pk(float a, float b) {
    u64 r; asm("mov.b64 %0, {%1, %2};" : "=l"(r) : "f"(a), "f"(b)); return r;
}
__device__ __forceinline__ void fma2(u64& d, u64 a, u64 b) {
    asm("fma.rn.f32x2 %0, %1, %2, %0;" : "+l"(d) : "l"(a), "l"(b));
}
__device__ __forceinline__ float2 up(u64 v) {
    float lo, hi; asm("mov.b64 {%0, %1}, %2;" : "=f"(lo), "=f"(hi) : "l"(v));
    float2 f; f.x = lo; f.y = hi; return f;
}

// ---------------------------------------------------------------------------
// Prep: zero state, slice patches into (n, b, s).
// ---------------------------------------------------------------------------
__global__ void prep_kernel(const float* __restrict__ gin)
{
    const int stride = gridDim.x * blockDim.x;
    const int t0 = blockIdx.x * blockDim.x + threadIdx.x;
    for (int i = t0; i < NCOL * COL_SEN; i += stride) {
        g_xobj0[i] = 0.0f;
        const int n = i >> 12, r = i & 4095;
        const int b  = r >> 6, s = r & 63;
        const int gh = n >> 5, gw = n & 31;
        const int ph = s >> 3, pw = s & 7;
        g_patch[i] = gin[b * 65536 + (gh * 8 + ph) * 256 + gw * 8 + pw];
    }
    for (int i = t0; i < NCOL * COL_LOC; i += stride)
        g_xloc[i] = 0.0f;
}

__device__ __forceinline__ float fast_tanh(float u) {
    float e = __expf(2.0f * u);
    return 1.0f - __fdividef(2.0f, e + 1.0f);
}

// ---------------------------------------------------------------------------
// One relaxation step. CTA n owns column n. 256 threads, 3 CTAs/SM.
// Shared (floats): sW 4352 | sWl 1024 | sx 4096 | sxl 1024 | sg 4096 |
//                  sctx 4096 -> 18688 floats = 74752 B.
// ---------------------------------------------------------------------------
constexpr int SH_FLOATS = 4352 + 1024 + 4096 + 1024 + 4096 + 4096;

__global__ void __launch_bounds__(256, 3) step_kernel(
    const float* __restrict__ Wobj,
    const float* __restrict__ Wloc,
    float* __restrict__ out_x,
    int step)
{
    extern __shared__ float sh[];
    float* sW   = sh;            // [o*68 + s]   (padded)
    float* sWl  = sh + 4352;     // [l*64 + s]
    float* sx   = sh + 5376;     // [b*64 + o]
    float* sxl  = sh + 9472;     // [b*16 + l]
    float* sg   = sh + 10496;    // [b*64 + s]
    float* sctx = sh + 14592;    // [b*64 + o]

    const int n   = blockIdx.x;
    const int tid = threadIdx.x;
    const int b0  = (tid >> 4) << 2;   // batch tile base (4 rows)
    const int c0  = (tid & 15) << 2;   // fwd s-tile base (4 cols, contiguous)
    const int oc  = tid & 15;          // bwd o base (stride-16 columns)

    const float* __restrict__ xin = (step & 1) ? g_xobj1 : g_xobj0;
    float* __restrict__ xoutbuf   = (step & 1) ? g_xobj0 : g_xobj1;
    float* __restrict__ xout      = (step == STEPS - 1) ? out_x : xoutbuf;

    // ---- lateral context (L2 loads, issued early) -> sctx ----
    {
        const int gh = n >> 5, gw = n & 31;
        const bool mu = gh > 0, md = gh < GRID_H - 1, ml = gw > 0, mr = gw < GRID_W - 1;
        const float inv = 1.0f / (float)((int)mu + (int)md + (int)ml + (int)mr);
        #pragma unroll
        for (int i = 0; i < 4; i++) {
            const int off = (b0 + i) * 64 + c0;
            float ax = 0.f, ay = 0.f, az = 0.f, aw = 0.f;
            if (mu) { float4 v = *(const float4*)&xin[(((long)(n - GRID_W)) << 12) + off]; ax += v.x; ay += v.y; az += v.z; aw += v.w; }
            if (md) { float4 v = *(const float4*)&xin[(((long)(n + GRID_W)) << 12) + off]; ax += v.x; ay += v.y; az += v.z; aw += v.w; }
            if (ml) { float4 v = *(const float4*)&xin[(((long)(n - 1))      << 12) + off]; ax += v.x; ay += v.y; az += v.z; aw += v.w; }
            if (mr) { float4 v = *(const float4*)&xin[(((long)(n + 1))      << 12) + off]; ax += v.x; ay += v.y; az += v.z; aw += v.w; }
            float4 o4; o4.x = ax * inv; o4.y = ay * inv; o4.z = az * inv; o4.w = aw * inv;
            *(float4*)&sctx[off] = o4;
        }
    }

    // ---- fill smem: W (padded rows), x, Wl, xl ----
    {
        const float4* wsrc = (const float4*)(Wobj + ((long)n << 12));
        #pragma unroll
        for (int k = 0; k < 4; k++) {
            const int e = tid + 256 * k;        // float4 index
            const int o = e >> 4, s4 = e & 15;
            *(float4*)&sW[o * SWS + (s4 << 2)] = wsrc[e];
        }
        const float4* xsrc = (const float4*)(xin + ((long)n << 12));
        float4* xdst = (float4*)sx;
        #pragma unroll
        for (int k = 0; k < 4; k++)
            xdst[tid + 256 * k] = xsrc[tid + 256 * k];
        ((float4*)sWl)[tid] = ((const float4*)(Wloc   + ((long)n << 10)))[tid];
        ((float4*)sxl)[tid] = ((const float4*)(g_xloc + ((long)n << 10)))[tid];
    }
    __syncthreads();

    // ---- forward: u = x_obj @ W_obj + x_loc @ W_loc (f32x2, c-paired acc) ----
    u64 accC[4][2];
    #pragma unroll
    for (int i = 0; i < 4; i++) { accC[i][0] = pk(0.f, 0.f); accC[i][1] = accC[i][0]; }

    #pragma unroll 4
    for (int o = 0; o < OBJ; o += 4) {
        u64 wp[4][2];
        #pragma unroll
        for (int j = 0; j < 4; j++) {
            float4 t = *(const float4*)&sW[(o + j) * SWS + c0];
            wp[j][0] = pk(t.x, t.y); wp[j][1] = pk(t.z, t.w);
        }
        #pragma unroll
        for (int i = 0; i < 4; i++) {
            float4 t = *(const float4*)&sx[(b0 + i) * 64 + o];
            float xs[4] = {t.x, t.y, t.z, t.w};
            #pragma unroll
            for (int k = 0; k < 4; k++) {
                u64 xd = pk(xs[k], xs[k]);
                fma2(accC[i][0], xd, wp[k][0]);
                fma2(accC[i][1], xd, wp[k][1]);
            }
        }
    }

    // prefetch patch tiles (L2) while the loc-forward loop runs
    float4 p4[4];
    #pragma unroll
    for (int i = 0; i < 4; i++)
        p4[i] = *(const float4*)&g_patch[((long)n << 12) + (b0 + i) * 64 + c0];

    #pragma unroll
    for (int l = 0; l < LOC; l += 4) {
        u64 wp[4][2];
        #pragma unroll
        for (int j = 0; j < 4; j++) {
            float4 t = *(const float4*)&sWl[(l + j) * 64 + c0];
            wp[j][0] = pk(t.x, t.y); wp[j][1] = pk(t.z, t.w);
        }
        #pragma unroll
        for (int i = 0; i < 4; i++) {
            float4 t = *(const float4*)&sxl[(b0 + i) * 16 + l];
            float xs[4] = {t.x, t.y, t.z, t.w};
            #pragma unroll
            for (int k = 0; k < 4; k++) {
                u64 xd = pk(xs[k], xs[k]);
                fma2(accC[i][0], xd, wp[k][0]);
                fma2(accC[i][1], xd, wp[k][1]);
            }
        }
    }

    // ---- pointwise: pred, eps, g, energy ----
    float e_acc = 0.f;
    #pragma unroll
    for (int i = 0; i < 4; i++) {
        float2 u01 = up(accC[i][0]);
        float2 u23 = up(accC[i][1]);
        float uv[4] = {u01.x, u01.y, u23.x, u23.y};
        float pv[4] = {p4[i].x, p4[i].y, p4[i].z, p4[i].w};
        float gg[4];
        #pragma unroll
        for (int c = 0; c < 4; c++) {
            float pr  = fast_tanh(uv[c]);
            float eps = pv[c] - pr;
            e_acc += eps * eps;
            gg[c] = eps * (1.0f - pr * pr);
        }
        float4 g4; g4.x = gg[0]; g4.y = gg[1]; g4.z = gg[2]; g4.w = gg[3];
        *(float4*)&sg[(b0 + i) * 64 + c0] = g4;
    }
    __syncthreads();

    // ---- backward obj: dx_obj = g @ W^T (f32x2, k-paired, pairs free) ----
    // thread covers o = oc + 16j; accB[i][j] is a pair over s (hadd at end)
    u64 accB[4][4];
    #pragma unroll
    for (int i = 0; i < 4; i++)
        #pragma unroll
        for (int j = 0; j < 4; j++) accB[i][j] = pk(0.f, 0.f);

    #pragma unroll 4
    for (int s = 0; s < SEN; s += 4) {
        u64 gp[4][2], wp[4][2];
        #pragma unroll
        for (int i = 0; i < 4; i++) {
            float4 t = *(const float4*)&sg[(b0 + i) * 64 + s];
            gp[i][0] = pk(t.x, t.y); gp[i][1] = pk(t.z, t.w);
        }
        #pragma unroll
        for (int j = 0; j < 4; j++) {
            float4 t = *(const float4*)&sW[(oc + 16 * j) * SWS + s];
            wp[j][0] = pk(t.x, t.y); wp[j][1] = pk(t.z, t.w);
        }
        #pragma unroll
        for (int i = 0; i < 4; i++)
            #pragma unroll
            for (int j = 0; j < 4; j++) {
                fma2(accB[i][j], gp[i][0], wp[j][0]);
                fma2(accB[i][j], gp[i][1], wp[j][1]);
            }
    }
    // update x_obj at o = oc + 16j (coalesced scalar stores)
    #pragma unroll
    for (int i = 0; i < 4; i++) {
        #pragma unroll
        for (int j = 0; j < 4; j++) {
            float2 h = up(accB[i][j]);
            const float dxo = h.x + h.y;
            const int idx = (b0 + i) * 64 + oc + 16 * j;
            const float xo = sx[idx];
            const float cv = sctx[idx];
            xout[((long)n << 12) + idx] = xo + ETA * (dxo + cv - xo);
        }
    }

    // ---- backward loc: dx_loc = g @ W_loc^T (f32x2, k-paired) ----
    {
        const int bl = tid >> 2;
        const int l0 = (tid & 3) << 2;
        u64 a3p[4];
        #pragma unroll
        for (int lp = 0; lp < 4; lp++) a3p[lp] = pk(0.f, 0.f);
        #pragma unroll 4
        for (int s = 0; s < SEN; s += 4) {
            float4 gq = *(const float4*)&sg[bl * 64 + s];
            u64 g01 = pk(gq.x, gq.y), g23 = pk(gq.z, gq.w);
            #pragma unroll
            for (int lp = 0; lp < 4; lp++) {
                float4 w = *(const float4*)&sWl[(l0 + lp) * 64 + s];
                fma2(a3p[lp], g01, pk(w.x, w.y));
                fma2(a3p[lp], g23, pk(w.z, w.w));
            }
        }
        float a3[4];
        #pragma unroll
        for (int lp = 0; lp < 4; lp++) { float2 h = up(a3p[lp]); a3[lp] = h.x + h.y; }
        float4 xl = *(const float4*)&sxl[bl * 16 + l0];
        float4 ov;
        ov.x = xl.x + ETA * a3[0]; ov.y = xl.y + ETA * a3[1];
        ov.z = xl.z + ETA * a3[2]; ov.w = xl.w + ETA * a3[3];
        *(float4*)&g_xloc[((long)n << 10) + bl * 16 + l0] = ov;
    }

    // ---- energy: shuffle reduce + 8 partials via sg (reused) ----
    __syncthreads();
    #pragma unroll
    for (int w = 16; w > 0; w >>= 1)
        e_acc += __shfl_down_sync(0xffffffffu, e_acc, w);
    if ((tid & 31) == 0) sg[tid >> 5] = e_acc;
    __syncthreads();
    if (tid == 0) {
        float s = 0.f;
        #pragma unroll
        for (int w = 0; w < 8; w++) s += sg[w];
        g_epart[step * NCOL + n] = s;
    }
}

// ---------------------------------------------------------------------------
// Finalize: fixed-order sum of 1024 partials per step -> energy_hist.
// ---------------------------------------------------------------------------
__global__ void finalize_kernel(float* __restrict__ out)
{
    const int step = blockIdx.x;
    const int tid  = threadIdx.x;
    __shared__ float r[256];
    float s = g_epart[step * NCOL + tid]
            + g_epart[step * NCOL + tid + 256]
            + g_epart[step * NCOL + tid + 512]
            + g_epart[step * NCOL + tid + 768];
    r[tid] = s;
    __syncthreads();
    #pragma unroll
    for (int w = 128; w > 0; w >>= 1) {
        if (tid < w) r[tid] += r[tid + w];
        __syncthreads();
    }
    if (tid == 0) out[(long)NCOL * COL_OBJ + step] = 0.5f * r[0];
}

// ---------------------------------------------------------------------------
extern "C" void kernel_launch(void* const* d_in, const int* in_sizes, int n_in,
                              void* d_out, int out_size)
{
    const float* gin  = (const float*)d_in[0];  // global_input (64, 65536)
    const float* Wobj = (const float*)d_in[1];  // (1024, 64, 64)
    const float* Wloc = (const float*)d_in[2];  // (1024, 16, 64)
    float* out = (float*)d_out;                 // x_obj (1024*64*64) ++ energy (20)

    constexpr int SMEM_BYTES = SH_FLOATS * (int)sizeof(float);  // 74752
    cudaFuncSetAttribute(step_kernel, cudaFuncAttributeMaxDynamicSharedMemorySize, SMEM_BYTES);

    prep_kernel<<<1024, 256>>>(gin);
    for (int step = 0; step < STEPS; step++) {
        step_kernel<<<NCOL, 256, SMEM_BYTES>>>(Wobj, Wloc, out, step);
    }
    finalize_kernel<<<STEPS, 256>>>(out);
}

// round 14
// speedup vs baseline: 1.3102x; 1.2390x over previous
#include <cuda_runtime.h>
#include <cuda_bf16.h>

// ---------------------------------------------------------------------------
// CorticalGrid R5 (resubmit — broker timeout): tensor-core rewrite. All four
// GEMMs per column-step run on mma.sync.m16n8k16 bf16 with a 3-product hi/lo
// split (fp32-grade accuracy). Weights pre-split/padded/transposed once in
// prep; x / g split per step. Evidence: R1/R3/R4 all ~80us/step with L1tex
// ~78% and every other pipe idle -> LDS-bound; fragments cut wavefronts ~20x.
// ---------------------------------------------------------------------------

typedef unsigned int u32;

constexpr int GRID_H = 32, GRID_W = 32;
constexpr int NCOL   = GRID_H * GRID_W;   // 1024
constexpr int BATCH  = 64;
constexpr int OBJ    = 64;
constexpr int LOC    = 16;
constexpr int SEN    = 64;
constexpr int STEPS  = 20;
constexpr float ETA  = 0.05f;

constexpr int COL_OBJ = BATCH * OBJ;   // 4096
constexpr int COL_LOC = BATCH * LOC;   // 1024
constexpr int COL_SEN = BATCH * SEN;   // 4096

// padded word strides (1 word = 2 bf16)
constexpr int SW36 = 36;   // 64-wide rows padded to 72 bf16  (bank 4g+t, CF)
constexpr int SW12 = 12;   // 16-wide rows padded to 24 bf16  (bank 12g+t, CF)

constexpr int W64_WORDS = 64 * SW36;   // 2304
constexpr int WT16_WORDS = 64 * SW12;  // 768  ([s][l] / [b][l] arrays)
constexpr int WL_WORDS = 16 * SW36;    // 576  ([l][s] array)

// fp32 state + static data
__device__ float g_xobj0[NCOL * COL_OBJ];
__device__ float g_xobj1[NCOL * COL_OBJ];
__device__ float g_xloc [NCOL * COL_LOC];
__device__ float g_patch[NCOL * COL_SEN];
__device__ float g_epart[STEPS * NCOL];

// pre-split bf16 weights (packed words, padded layouts)
__device__ u32 g_Wh  [NCOL * W64_WORDS];   // W  [o][s]  hi
__device__ u32 g_Wlo [NCOL * W64_WORDS];   //            lo
__device__ u32 g_Wth [NCOL * W64_WORDS];   // W^T[s][o]  hi
__device__ u32 g_Wtlo[NCOL * W64_WORDS];   //            lo
__device__ u32 g_Wlh [NCOL * WL_WORDS];    // Wl [l][s]  hi
__device__ u32 g_Wllo[NCOL * WL_WORDS];
__device__ u32 g_Wlth[NCOL * WT16_WORDS];  // Wl^T[s][l] hi
__device__ u32 g_Wltlo[NCOL * WT16_WORDS];

__device__ __forceinline__ void split2(float v0, float v1, u32& hw, u32& lw) {
    __nv_bfloat162 h2 = __floats2bfloat162_rn(v0, v1);     // .x = v0 (low half)
    float h0 = __bfloat162float(h2.x);
    float h1 = __bfloat162float(h2.y);
    __nv_bfloat162 l2 = __floats2bfloat162_rn(v0 - h0, v1 - h1);
    hw = *reinterpret_cast<u32*>(&h2);
    lw = *reinterpret_cast<u32*>(&l2);
}

__device__ __forceinline__ void mma_bf16(float* c, const u32* a, u32 b0, u32 b1) {
    asm volatile(
        "mma.sync.aligned.m16n8k16.row.col.f32.bf16.bf16.f32 "
        "{%0,%1,%2,%3}, {%4,%5,%6,%7}, {%8,%9}, {%0,%1,%2,%3};"
        : "+f"(c[0]), "+f"(c[1]), "+f"(c[2]), "+f"(c[3])
        : "r"(a[0]), "r"(a[1]), "r"(a[2]), "r"(a[3]), "r"(b0), "r"(b1));
}

__device__ __forceinline__ float fast_tanh(float u) {
    float e = __expf(2.0f * u);
    return 1.0f - __fdividef(2.0f, e + 1.0f);
}

// ---------------------------------------------------------------------------
// Prep: one CTA per column. Patches, zero state, build split/padded weights.
// ---------------------------------------------------------------------------
__global__ void prep_kernel(const float* __restrict__ gin,
                            const float* __restrict__ Wobj,
                            const float* __restrict__ Wloc)
{
    const int col = blockIdx.x;
    const int tid = threadIdx.x;
    const long wb = (long)col << 12;            // W_obj base (4096 per col)
    const long lb = (long)col << 10;            // W_loc base (1024 per col)

    // patches + zero x_obj
    for (int i = tid; i < COL_SEN; i += 256) {
        g_xobj0[wb + i] = 0.0f;
        const int b = i >> 6, s = i & 63;
        const int gh = col >> 5, gw = col & 31;
        const int ph = s >> 3, pw = s & 7;
        g_patch[wb + i] = gin[b * 65536 + (gh * 8 + ph) * 256 + gw * 8 + pw];
    }
    for (int i = tid; i < COL_LOC; i += 256)
        g_xloc[lb + i] = 0.0f;

    // W [o][s] hi/lo
    for (int w = tid; w < W64_WORDS; w += 256) {
        const int o = w / SW36, sp = w % SW36;
        u32 hw = 0, lw = 0;
        if (sp < 32) split2(Wobj[wb + o * 64 + 2 * sp], Wobj[wb + o * 64 + 2 * sp + 1], hw, lw);
        g_Wh [(long)col * W64_WORDS + w] = hw;
        g_Wlo[(long)col * W64_WORDS + w] = lw;
    }
    // W^T [s][o] hi/lo
    for (int w = tid; w < W64_WORDS; w += 256) {
        const int s = w / SW36, op = w % SW36;
        u32 hw = 0, lw = 0;
        if (op < 32) split2(Wobj[wb + (2 * op) * 64 + s], Wobj[wb + (2 * op + 1) * 64 + s], hw, lw);
        g_Wth [(long)col * W64_WORDS + w] = hw;
        g_Wtlo[(long)col * W64_WORDS + w] = lw;
    }
    // Wl [l][s] hi/lo
    for (int w = tid; w < WL_WORDS; w += 256) {
        const int l = w / SW36, sp = w % SW36;
        u32 hw = 0, lw = 0;
        if (sp < 32) split2(Wloc[lb + l * 64 + 2 * sp], Wloc[lb + l * 64 + 2 * sp + 1], hw, lw);
        g_Wlh [(long)col * WL_WORDS + w] = hw;
        g_Wllo[(long)col * WL_WORDS + w] = lw;
    }
    // Wl^T [s][l] hi/lo
    for (int w = tid; w < WT16_WORDS; w += 256) {
        const int s = w / SW12, lp = w % SW12;
        u32 hw = 0, lw = 0;
        if (lp < 8) split2(Wloc[lb + (2 * lp) * 64 + s], Wloc[lb + (2 * lp + 1) * 64 + s], hw, lw);
        g_Wlth [(long)col * WT16_WORDS + w] = hw;
        g_Wltlo[(long)col * WT16_WORDS + w] = lw;
    }
}

// ---------------------------------------------------------------------------
// Smem word offsets
// ---------------------------------------------------------------------------
constexpr int OXH   = 0;                    // x  hi  [b][36w]
constexpr int OXL   = OXH   + W64_WORDS;    // x  lo
constexpr int OWTH  = OXL   + W64_WORDS;    // W^T hi
constexpr int OWTL  = OWTH  + W64_WORDS;
constexpr int OWH   = OWTL  + W64_WORDS;    // W hi
constexpr int OWLO  = OWH   + W64_WORDS;
constexpr int OGH   = OWLO  + W64_WORDS;    // g hi
constexpr int OGLO  = OGH   + W64_WORDS;
constexpr int OWLTH = OGLO  + W64_WORDS;    // Wl^T hi [s][12w]
constexpr int OWLTL = OWLTH + WT16_WORDS;
constexpr int OWLH  = OWLTL + WT16_WORDS;   // Wl hi [l][36w]
constexpr int OWLL  = OWLH  + WL_WORDS;
constexpr int OXLH  = OWLL  + WL_WORDS;     // xl hi [b][12w]
constexpr int OXLL  = OXLH  + WT16_WORDS;
constexpr int OCTX  = OXLL  + WT16_WORDS;   // ctx f32 [b][68]
constexpr int ORED  = OCTX  + 64 * 68;
constexpr int SH_WORDS = ORED + 16;         // 27024 words = 108096 B

// ---------------------------------------------------------------------------
// One relaxation step. CTA = column. 256 threads = 8 warps. 2 CTAs/SM.
// ---------------------------------------------------------------------------
__global__ void __launch_bounds__(256) step_kernel(float* __restrict__ out_x, int step)
{
    extern __shared__ u32 shw[];
    float* sctx  = (float*)(shw + OCTX);
    float* sredf = (float*)(shw + ORED);

    const int col = blockIdx.x;
    const int tid = threadIdx.x;
    const int wid = tid >> 5;
    const int lane = tid & 31;
    const int g = lane >> 2;           // group row
    const int t = lane & 3;            // thread-in-group

    const int m0  = (wid & 3) * 16;    // batch rows of this warp
    const int n0  = (wid >> 2) * 32;   // output cols (4 n8 tiles)
    const int nl0 = (wid >> 2) * 8;    // loc cols (1 n8 tile)

    const float* __restrict__ xin = (step & 1) ? g_xobj1 : g_xobj0;
    float* __restrict__ xoutbuf   = (step & 1) ? g_xobj0 : g_xobj1;
    float* __restrict__ xout      = (step == STEPS - 1) ? out_x : xoutbuf;

    // ---------------- fill phase ----------------
    // ctx (fp32, stride 68)
    {
        const int b0 = (tid >> 4) << 2;
        const int c0 = (tid & 15) << 2;
        const int gh = col >> 5, gw = col & 31;
        const bool mu = gh > 0, md = gh < GRID_H - 1, ml = gw > 0, mr = gw < GRID_W - 1;
        const float inv = 1.0f / (float)((int)mu + (int)md + (int)ml + (int)mr);
        #pragma unroll
        for (int i = 0; i < 4; i++) {
            const int off = (b0 + i) * 64 + c0;
            float ax = 0.f, ay = 0.f, az = 0.f, aw = 0.f;
            if (mu) { float4 v = *(const float4*)&xin[(((long)(col - GRID_W)) << 12) + off]; ax += v.x; ay += v.y; az += v.z; aw += v.w; }
            if (md) { float4 v = *(const float4*)&xin[(((long)(col + GRID_W)) << 12) + off]; ax += v.x; ay += v.y; az += v.z; aw += v.w; }
            if (ml) { float4 v = *(const float4*)&xin[(((long)(col - 1))      << 12) + off]; ax += v.x; ay += v.y; az += v.z; aw += v.w; }
            if (mr) { float4 v = *(const float4*)&xin[(((long)(col + 1))      << 12) + off]; ax += v.x; ay += v.y; az += v.z; aw += v.w; }
            float4 o4; o4.x = ax * inv; o4.y = ay * inv; o4.z = az * inv; o4.w = aw * inv;
            *(float4*)&sctx[(b0 + i) * 68 + c0] = o4;
        }
    }
    // weight copies (pre-padded, plain float4 memcpy)
    {
        const float4* s1 = (const float4*)(g_Wth  + (long)col * W64_WORDS);
        const float4* s2 = (const float4*)(g_Wtlo + (long)col * W64_WORDS);
        const float4* s3 = (const float4*)(g_Wh   + (long)col * W64_WORDS);
        const float4* s4 = (const float4*)(g_Wlo  + (long)col * W64_WORDS);
        float4* d1 = (float4*)(shw + OWTH); float4* d2 = (float4*)(shw + OWTL);
        float4* d3 = (float4*)(shw + OWH);  float4* d4 = (float4*)(shw + OWLO);
        for (int i = tid; i < W64_WORDS / 4; i += 256) {   // 576 float4 each
            d1[i] = s1[i]; d2[i] = s2[i]; d3[i] = s3[i]; d4[i] = s4[i];
        }
        const float4* s5 = (const float4*)(g_Wlth  + (long)col * WT16_WORDS);
        const float4* s6 = (const float4*)(g_Wltlo + (long)col * WT16_WORDS);
        float4* d5 = (float4*)(shw + OWLTH); float4* d6 = (float4*)(shw + OWLTL);
        for (int i = tid; i < WT16_WORDS / 4; i += 256) { d5[i] = s5[i]; d6[i] = s6[i]; }
        const float4* s7 = (const float4*)(g_Wlh  + (long)col * WL_WORDS);
        const float4* s8 = (const float4*)(g_Wllo + (long)col * WL_WORDS);
        float4* d7 = (float4*)(shw + OWLH); float4* d8 = (float4*)(shw + OWLL);
        for (int i = tid; i < WL_WORDS / 4; i += 256) { d7[i] = s7[i]; d8[i] = s8[i]; }
    }
    // x -> bf16 hi/lo (2048 packed words)
    for (int w = tid; w < 2048; w += 256) {
        const int b = w >> 5, sp = w & 31;
        float2 v = *(const float2*)&xin[((long)col << 12) + (b << 6) + 2 * sp];
        u32 hw, lw; split2(v.x, v.y, hw, lw);
        shw[OXH + b * SW36 + sp] = hw;
        shw[OXL + b * SW36 + sp] = lw;
    }
    // xl -> bf16 hi/lo (512 packed words)
    for (int w = tid; w < 512; w += 256) {
        const int b = w >> 3, lp = w & 7;
        float2 v = *(const float2*)&g_xloc[((long)col << 10) + (b << 4) + 2 * lp];
        u32 hw, lw; split2(v.x, v.y, hw, lw);
        shw[OXLH + b * SW12 + lp] = hw;
        shw[OXLL + b * SW12 + lp] = lw;
    }
    __syncthreads();

    // ---------------- forward: u = x@W + xl@Wl ----------------
    float c[4][4];
    #pragma unroll
    for (int j = 0; j < 4; j++) { c[j][0]=0.f; c[j][1]=0.f; c[j][2]=0.f; c[j][3]=0.f; }

    #pragma unroll
    for (int kc = 0; kc < 4; kc++) {
        const int kw = kc * 8 + t;
        u32 ah[4], al[4];
        ah[0] = shw[OXH + (m0 + g    ) * SW36 + kw];
        ah[1] = shw[OXH + (m0 + g + 8) * SW36 + kw];
        ah[2] = shw[OXH + (m0 + g    ) * SW36 + kw + 4];
        ah[3] = shw[OXH + (m0 + g + 8) * SW36 + kw + 4];
        al[0] = shw[OXL + (m0 + g    ) * SW36 + kw];
        al[1] = shw[OXL + (m0 + g + 8) * SW36 + kw];
        al[2] = shw[OXL + (m0 + g    ) * SW36 + kw + 4];
        al[3] = shw[OXL + (m0 + g + 8) * SW36 + kw + 4];
        #pragma unroll
        for (int j = 0; j < 4; j++) {
            const int n = n0 + 8 * j;
            u32 bh0 = shw[OWTH + (n + g) * SW36 + kw];
            u32 bh1 = shw[OWTH + (n + g) * SW36 + kw + 4];
            u32 bl0 = shw[OWTL + (n + g) * SW36 + kw];
            u32 bl1 = shw[OWTL + (n + g) * SW36 + kw + 4];
            mma_bf16(c[j], ah, bh0, bh1);
            mma_bf16(c[j], ah, bl0, bl1);
            mma_bf16(c[j], al, bh0, bh1);
        }
    }
    // loc forward (K = 16, single chunk)
    {
        u32 ah[4], al[4];
        ah[0] = shw[OXLH + (m0 + g    ) * SW12 + t];
        ah[1] = shw[OXLH + (m0 + g + 8) * SW12 + t];
        ah[2] = shw[OXLH + (m0 + g    ) * SW12 + t + 4];
        ah[3] = shw[OXLH + (m0 + g + 8) * SW12 + t + 4];
        al[0] = shw[OXLL + (m0 + g    ) * SW12 + t];
        al[1] = shw[OXLL + (m0 + g + 8) * SW12 + t];
        al[2] = shw[OXLL + (m0 + g    ) * SW12 + t + 4];
        al[3] = shw[OXLL + (m0 + g + 8) * SW12 + t + 4];
        #pragma unroll
        for (int j = 0; j < 4; j++) {
            const int n = n0 + 8 * j;
            u32 bh0 = shw[OWLTH + (n + g) * SW12 + t];
            u32 bh1 = shw[OWLTH + (n + g) * SW12 + t + 4];
            u32 bl0 = shw[OWLTL + (n + g) * SW12 + t];
            u32 bl1 = shw[OWLTL + (n + g) * SW12 + t + 4];
            mma_bf16(c[j], ah, bh0, bh1);
            mma_bf16(c[j], ah, bl0, bl1);
            mma_bf16(c[j], al, bh0, bh1);
        }
    }

    // ---------------- pointwise: pred, eps, g, energy ----------------
    float e_acc = 0.f;
    #pragma unroll
    for (int j = 0; j < 4; j++) {
        const int n = n0 + 8 * j;
        const int cA = n + 2 * t;
        float2 p0 = *(const float2*)&g_patch[((long)col << 12) + (m0 + g    ) * 64 + cA];
        float2 p1 = *(const float2*)&g_patch[((long)col << 12) + (m0 + g + 8) * 64 + cA];
        float pr0 = fast_tanh(c[j][0]), pr1 = fast_tanh(c[j][1]);
        float pr2 = fast_tanh(c[j][2]), pr3 = fast_tanh(c[j][3]);
        float e0 = p0.x - pr0, e1 = p0.y - pr1, e2 = p1.x - pr2, e3 = p1.y - pr3;
        e_acc += e0 * e0 + e1 * e1 + e2 * e2 + e3 * e3;
        float g0 = e0 * (1.0f - pr0 * pr0), g1 = e1 * (1.0f - pr1 * pr1);
        float g2 = e2 * (1.0f - pr2 * pr2), g3 = e3 * (1.0f - pr3 * pr3);
        u32 hw, lw;
        split2(g0, g1, hw, lw);
        shw[OGH  + (m0 + g) * SW36 + (n >> 1) + t] = hw;
        shw[OGLO + (m0 + g) * SW36 + (n >> 1) + t] = lw;
        split2(g2, g3, hw, lw);
        shw[OGH  + (m0 + g + 8) * SW36 + (n >> 1) + t] = hw;
        shw[OGLO + (m0 + g + 8) * SW36 + (n >> 1) + t] = lw;
    }
    __syncthreads();

    // ---------------- backward: dx = g@W^T, dxl = g@Wl^T ----------------
    float d[4][4], dl[4];
    #pragma unroll
    for (int j = 0; j < 4; j++) { d[j][0]=0.f; d[j][1]=0.f; d[j][2]=0.f; d[j][3]=0.f; }
    dl[0]=0.f; dl[1]=0.f; dl[2]=0.f; dl[3]=0.f;

    #pragma unroll
    for (int kc = 0; kc < 4; kc++) {
        const int kw = kc * 8 + t;
        u32 ah[4], al[4];
        ah[0] = shw[OGH  + (m0 + g    ) * SW36 + kw];
        ah[1] = shw[OGH  + (m0 + g + 8) * SW36 + kw];
        ah[2] = shw[OGH  + (m0 + g    ) * SW36 + kw + 4];
        ah[3] = shw[OGH  + (m0 + g + 8) * SW36 + kw + 4];
        al[0] = shw[OGLO + (m0 + g    ) * SW36 + kw];
        al[1] = shw[OGLO + (m0 + g + 8) * SW36 + kw];
        al[2] = shw[OGLO + (m0 + g    ) * SW36 + kw + 4];
        al[3] = shw[OGLO + (m0 + g + 8) * SW36 + kw + 4];
        #pragma unroll
        for (int j = 0; j < 4; j++) {
            const int n = n0 + 8 * j;
            u32 bh0 = shw[OWH  + (n + g) * SW36 + kw];
            u32 bh1 = shw[OWH  + (n + g) * SW36 + kw + 4];
            u32 bl0 = shw[OWLO + (n + g) * SW36 + kw];
            u32 bl1 = shw[OWLO + (n + g) * SW36 + kw + 4];
            mma_bf16(d[j], ah, bh0, bh1);
            mma_bf16(d[j], ah, bl0, bl1);
            mma_bf16(d[j], al, bh0, bh1);
        }
        {   // loc tile (n = l at nl0)
            u32 bh0 = shw[OWLH + (nl0 + g) * SW36 + kw];
            u32 bh1 = shw[OWLH + (nl0 + g) * SW36 + kw + 4];
            u32 bl0 = shw[OWLL + (nl0 + g) * SW36 + kw];
            u32 bl1 = shw[OWLL + (nl0 + g) * SW36 + kw + 4];
            mma_bf16(dl, ah, bh0, bh1);
            mma_bf16(dl, ah, bl0, bl1);
            mma_bf16(dl, al, bh0, bh1);
        }
    }

    // ---------------- epilogue: state updates ----------------
    #pragma unroll
    for (int j = 0; j < 4; j++) {
        const int n = n0 + 8 * j;
        const int cA = n + 2 * t;
        const long i0 = ((long)col << 12) + (m0 + g    ) * 64 + cA;
        const long i1 = ((long)col << 12) + (m0 + g + 8) * 64 + cA;
        float2 x0 = *(const float2*)&xin[i0];
        float2 x1 = *(const float2*)&xin[i1];
        float2 c0 = *(const float2*)&sctx[(m0 + g    ) * 68 + cA];
        float2 c1 = *(const float2*)&sctx[(m0 + g + 8) * 68 + cA];
        float2 o0, o1;
        o0.x = x0.x + ETA * (d[j][0] + c0.x - x0.x);
        o0.y = x0.y + ETA * (d[j][1] + c0.y - x0.y);
        o1.x = x1.x + ETA * (d[j][2] + c1.x - x1.x);
        o1.y = x1.y + ETA * (d[j][3] + c1.y - x1.y);
        *(float2*)&xout[i0] = o0;
        *(float2*)&xout[i1] = o1;
    }
    {   // x_loc update (each (b,l) owned exactly once)
        const int cL = nl0 + 2 * t;
        const long i0 = ((long)col << 10) + (m0 + g    ) * 16 + cL;
        const long i1 = ((long)col << 10) + (m0 + g + 8) * 16 + cL;
        float2 x0 = *(const float2*)&g_xloc[i0];
        float2 x1 = *(const float2*)&g_xloc[i1];
        float2 o0, o1;
        o0.x = x0.x + ETA * dl[0];
        o0.y = x0.y + ETA * dl[1];
        o1.x = x1.x + ETA * dl[2];
        o1.y = x1.y + ETA * dl[3];
        *(float2*)&g_xloc[i0] = o0;
        *(float2*)&g_xloc[i1] = o1;
    }

    // ---------------- energy ----------------
    #pragma unroll
    for (int w = 16; w > 0; w >>= 1)
        e_acc += __shfl_down_sync(0xffffffffu, e_acc, w);
    if (lane == 0) sredf[wid] = e_acc;
    __syncthreads();
    if (tid == 0) {
        float s = 0.f;
        #pragma unroll
        for (int w = 0; w < 8; w++) s += sredf[w];
        g_epart[step * NCOL + col] = s;
    }
}

// ---------------------------------------------------------------------------
// Finalize: fixed-order sum of 1024 partials per step -> energy_hist.
// ---------------------------------------------------------------------------
__global__ void finalize_kernel(float* __restrict__ out)
{
    const int step = blockIdx.x;
    const int tid  = threadIdx.x;
    __shared__ float r[256];
    float s = g_epart[step * NCOL + tid]
            + g_epart[step * NCOL + tid + 256]
            + g_epart[step * NCOL + tid + 512]
            + g_epart[step * NCOL + tid + 768];
    r[tid] = s;
    __syncthreads();
    #pragma unroll
    for (int w = 128; w > 0; w >>= 1) {
        if (tid < w) r[tid] += r[tid + w];
        __syncthreads();
    }
    if (tid == 0) out[(long)NCOL * COL_OBJ + step] = 0.5f * r[0];
}

// ---------------------------------------------------------------------------
extern "C" void kernel_launch(void* const* d_in, const int* in_sizes, int n_in,
                              void* d_out, int out_size)
{
    const float* gin  = (const float*)d_in[0];  // global_input (64, 65536)
    const float* Wobj = (const float*)d_in[1];  // (1024, 64, 64)
    const float* Wloc = (const float*)d_in[2];  // (1024, 16, 64)
    float* out = (float*)d_out;                 // x_obj ++ energy(20)

    constexpr int SMEM_BYTES = SH_WORDS * (int)sizeof(u32);  // 108096
    cudaFuncSetAttribute(step_kernel, cudaFuncAttributeMaxDynamicSharedMemorySize, SMEM_BYTES);

    prep_kernel<<<NCOL, 256>>>(gin, Wobj, Wloc);
    for (int step = 0; step < STEPS; step++) {
        step_kernel<<<NCOL, 256, SMEM_BYTES>>>(out, step);
    }
    finalize_kernel<<<STEPS, 256>>>(out);
}